// round 2
// baseline (speedup 1.0000x reference)
#include <cuda_runtime.h>
#include <math.h>

#define Bsz 4
#define Lseq 2048
#define Dmodel 1024
#define Hheads 16
#define DffDim 4096
#define MAXDIST 512
#define HDdim 64

// Scratch (allocation-free rule: __device__ globals)
__device__ float g_qkv[Bsz*Lseq*3*Dmodel];   // 25.2M floats
__device__ float g_ctx[Bsz*Lseq*Dmodel];
__device__ float g_tmp[Bsz*Lseq*Dmodel];
__device__ float g_x1 [Bsz*Lseq*Dmodel];
__device__ float g_hb [Bsz*Lseq*DffDim];     // 33.6M floats

// ---------------------------------------------------------------------------
// SGEMM: C[M,N] = A[M,K] @ B[K,N], 128x128 block tile, 8x8 per thread, BK=8.
// EPI: 0 = none, 1 = +bias[n] +res[m,n], 2 = +bias[n] then exact GELU.
// All dims are multiples of tile sizes for this problem (no bounds checks).
// ---------------------------------------------------------------------------
template<int EPI>
__global__ __launch_bounds__(256)
void sgemm_kernel(const float* __restrict__ A, const float* __restrict__ B,
                  float* __restrict__ C, int M, int N, int K,
                  const float* __restrict__ bias, const float* __restrict__ res)
{
    __shared__ float As[8][128];
    __shared__ float Bs[8][128];
    const int tid = threadIdx.x;
    const int bx = blockIdx.x, by = blockIdx.y;
    const int ar = tid >> 1, ac = (tid & 1) << 2;   // A tile: 128 rows x 8 cols
    const int br = tid >> 5, bc = (tid & 31) << 2;  // B tile: 8 rows x 128 cols
    const float* Ap = A + (size_t)(by*128 + ar)*K + ac;
    const float* Bp = B + (size_t)br*N + bx*128 + bc;
    const int tx = tid & 15, ty = tid >> 4;

    float acc[8][8];
#pragma unroll
    for (int i = 0; i < 8; i++)
#pragma unroll
        for (int j = 0; j < 8; j++) acc[i][j] = 0.f;

    for (int k0 = 0; k0 < K; k0 += 8) {
        float4 av = *(const float4*)(Ap + k0);
        float4 bv = *(const float4*)(Bp + (size_t)k0*N);
        As[ac+0][ar] = av.x; As[ac+1][ar] = av.y;
        As[ac+2][ar] = av.z; As[ac+3][ar] = av.w;
        *(float4*)&Bs[br][bc] = bv;
        __syncthreads();
#pragma unroll
        for (int kk = 0; kk < 8; kk++) {
            float a[8], b[8];
            *(float4*)&a[0] = *(const float4*)&As[kk][ty*8];
            *(float4*)&a[4] = *(const float4*)&As[kk][ty*8+4];
            *(float4*)&b[0] = *(const float4*)&Bs[kk][tx*8];
            *(float4*)&b[4] = *(const float4*)&Bs[kk][tx*8+4];
#pragma unroll
            for (int i = 0; i < 8; i++)
#pragma unroll
                for (int j = 0; j < 8; j++)
                    acc[i][j] = fmaf(a[i], b[j], acc[i][j]);
        }
        __syncthreads();
    }

    const int row0 = by*128 + ty*8;
    const int col0 = bx*128 + tx*8;
    float bb[8];
    if (EPI != 0) {
#pragma unroll
        for (int j = 0; j < 8; j++) bb[j] = bias[col0 + j];
    }
#pragma unroll
    for (int i = 0; i < 8; i++) {
        float v[8];
#pragma unroll
        for (int j = 0; j < 8; j++) {
            float t = acc[i][j];
            if (EPI != 0) t += bb[j];
            if (EPI == 1) t += res[(size_t)(row0+i)*N + col0 + j];
            if (EPI == 2) t = t * normcdff(t);   // exact GELU: x * Phi(x)
            v[j] = t;
        }
        *(float4*)&C[(size_t)(row0+i)*N + col0    ] = *(float4*)&v[0];
        *(float4*)&C[(size_t)(row0+i)*N + col0 + 4] = *(float4*)&v[4];
    }
}

// ---------------------------------------------------------------------------
// Flash attention: one block per (q-tile of 64, b*h). 256 threads = 16x16,
// each thread owns a 4x4 subtile of S (64x64) and of O (64 x HD=64).
// Online softmax; relative-position bias computed in-register.
// Shared: Q,K,V,P tiles at pitch 65 (bank-conflict mitigation) = 66560 B.
// ---------------------------------------------------------------------------
#define ATTN_SMEM (4*64*65*4)

__global__ __launch_bounds__(256)
void flash_attn_kernel(const float* __restrict__ qkv,
                       const float* __restrict__ bias_table,
                       float* __restrict__ ctx)
{
    extern __shared__ float sm[];
    float* Qs = sm;
    float* Ks = sm +   64*65;
    float* Vs = sm + 2*64*65;
    float* Ps = sm + 3*64*65;
    const int qt = blockIdx.x;
    const int bh = blockIdx.y;
    const int b = bh >> 4, h = bh & 15;
    const int tid = threadIdx.x;
    const int tx = tid & 15, ty = tid >> 4;
    const int q0 = qt * 64;
    const size_t rs = 3*Dmodel;
    const float* base = qkv + (size_t)(b*Lseq)*rs + h*HDdim;

    // Load Q tile (64 x 64)
    for (int idx = tid; idx < 64*16; idx += 256) {
        int r = idx >> 4, c4 = (idx & 15) << 2;
        float4 v = *(const float4*)(base + (size_t)(q0 + r)*rs + c4);
        Qs[r*65+c4+0] = v.x; Qs[r*65+c4+1] = v.y;
        Qs[r*65+c4+2] = v.z; Qs[r*65+c4+3] = v.w;
    }

    float m_i[4], l_i[4], O[4][4];
#pragma unroll
    for (int i = 0; i < 4; i++) {
        m_i[i] = -1e30f; l_i[i] = 0.f;
#pragma unroll
        for (int j = 0; j < 4; j++) O[i][j] = 0.f;
    }
    const float scale = 0.125f;  // HD^-0.5
    __syncthreads();

    for (int kt = 0; kt < Lseq/64; kt++) {
        const int k0 = kt*64;
        // Load K and V tiles
        for (int idx = tid; idx < 64*16; idx += 256) {
            int r = idx >> 4, c4 = (idx & 15) << 2;
            const float* kb = base + (size_t)(k0 + r)*rs + Dmodel + c4;
            float4 kv = *(const float4*)kb;
            Ks[r*65+c4+0] = kv.x; Ks[r*65+c4+1] = kv.y;
            Ks[r*65+c4+2] = kv.z; Ks[r*65+c4+3] = kv.w;
            float4 vv = *(const float4*)(kb + Dmodel);
            Vs[r*65+c4+0] = vv.x; Vs[r*65+c4+1] = vv.y;
            Vs[r*65+c4+2] = vv.z; Vs[r*65+c4+3] = vv.w;
        }
        __syncthreads();

        // S = Q @ K^T (4x4 per thread)
        float s[4][4];
#pragma unroll
        for (int i = 0; i < 4; i++)
#pragma unroll
            for (int j = 0; j < 4; j++) s[i][j] = 0.f;
        for (int d = 0; d < 64; d++) {
            float a[4], bv[4];
#pragma unroll
            for (int i = 0; i < 4; i++) a[i]  = Qs[(ty*4+i)*65 + d];
#pragma unroll
            for (int j = 0; j < 4; j++) bv[j] = Ks[(tx*4+j)*65 + d];
#pragma unroll
            for (int i = 0; i < 4; i++)
#pragma unroll
                for (int j = 0; j < 4; j++)
                    s[i][j] = fmaf(a[i], bv[j], s[i][j]);
        }
        // scale + relative-position bias
#pragma unroll
        for (int i = 0; i < 4; i++) {
            int qg = q0 + ty*4 + i;
#pragma unroll
            for (int j = 0; j < 4; j++) {
                int kg = k0 + tx*4 + j;
                int rel = kg - qg + (MAXDIST-1);
                rel = min(max(rel, 0), 2*MAXDIST-2);
                s[i][j] = fmaf(s[i][j], scale, __ldg(&bias_table[rel*Hheads + h]));
            }
        }
        // Online softmax per row (row reduce over 16 lanes of same ty)
#pragma unroll
        for (int i = 0; i < 4; i++) {
            float rmax = fmaxf(fmaxf(s[i][0], s[i][1]), fmaxf(s[i][2], s[i][3]));
#pragma unroll
            for (int o = 8; o >= 1; o >>= 1)
                rmax = fmaxf(rmax, __shfl_xor_sync(0xffffffffu, rmax, o));
            float mnew = fmaxf(m_i[i], rmax);
            float corr = __expf(m_i[i] - mnew);
            float rsum = 0.f;
#pragma unroll
            for (int j = 0; j < 4; j++) {
                float p = __expf(s[i][j] - mnew);
                Ps[(ty*4+i)*65 + tx*4 + j] = p;
                rsum += p;
            }
#pragma unroll
            for (int o = 8; o >= 1; o >>= 1)
                rsum += __shfl_xor_sync(0xffffffffu, rsum, o);
            l_i[i] = l_i[i]*corr + rsum;
            m_i[i] = mnew;
#pragma unroll
            for (int j = 0; j < 4; j++) O[i][j] *= corr;
        }
        __syncthreads();
        // O += P @ V
        for (int k = 0; k < 64; k++) {
            float a[4], bv[4];
#pragma unroll
            for (int i = 0; i < 4; i++) a[i]  = Ps[(ty*4+i)*65 + k];
#pragma unroll
            for (int j = 0; j < 4; j++) bv[j] = Vs[k*65 + tx*4 + j];
#pragma unroll
            for (int i = 0; i < 4; i++)
#pragma unroll
                for (int j = 0; j < 4; j++)
                    O[i][j] = fmaf(a[i], bv[j], O[i][j]);
        }
        __syncthreads();
    }

    // Write ctx in [B, L, H, HD] layout (contiguous D = h*64+d)
#pragma unroll
    for (int i = 0; i < 4; i++) {
        float inv = 1.f / l_i[i];
        int qg = q0 + ty*4 + i;
        float* cp = ctx + (size_t)(b*Lseq + qg)*Dmodel + h*HDdim + tx*4;
#pragma unroll
        for (int j = 0; j < 4; j++) cp[j] = O[i][j]*inv;
    }
}

// ---------------------------------------------------------------------------
// LayerNorm over rows of 1024. One block (256 thr) per row, float4 per thread.
// ---------------------------------------------------------------------------
__global__ __launch_bounds__(256)
void ln_kernel(const float* __restrict__ in, const float* __restrict__ gamma,
               const float* __restrict__ beta, float* __restrict__ out)
{
    __shared__ float red[16];
    const int row = blockIdx.x;
    const int tid = threadIdx.x;
    float4 v = ((const float4*)(in + (size_t)row*Dmodel))[tid];
    float s  = v.x + v.y + v.z + v.w;
    float sq = v.x*v.x + v.y*v.y + v.z*v.z + v.w*v.w;
#pragma unroll
    for (int o = 16; o >= 1; o >>= 1) {
        s  += __shfl_xor_sync(0xffffffffu, s,  o);
        sq += __shfl_xor_sync(0xffffffffu, sq, o);
    }
    const int wid = tid >> 5, lane = tid & 31;
    if (lane == 0) { red[wid] = s; red[wid+8] = sq; }
    __syncthreads();
    if (tid < 32) {
        float s2 = (lane < 8) ? red[lane]   : 0.f;
        float q2 = (lane < 8) ? red[lane+8] : 0.f;
#pragma unroll
        for (int o = 4; o >= 1; o >>= 1) {
            s2 += __shfl_xor_sync(0xffffffffu, s2, o);
            q2 += __shfl_xor_sync(0xffffffffu, q2, o);
        }
        if (lane == 0) { red[0] = s2; red[1] = q2; }
    }
    __syncthreads();
    const float mu  = red[0] * (1.f/Dmodel);
    const float var = red[1] * (1.f/Dmodel) - mu*mu;
    const float inv = rsqrtf(var + 1e-5f);
    const float4 g  = ((const float4*)gamma)[tid];
    const float4 be = ((const float4*)beta)[tid];
    float4 o;
    o.x = (v.x - mu)*inv*g.x + be.x;
    o.y = (v.y - mu)*inv*g.y + be.y;
    o.z = (v.z - mu)*inv*g.z + be.z;
    o.w = (v.w - mu)*inv*g.w + be.w;
    ((float4*)(out + (size_t)row*Dmodel))[tid] = o;
}

// ---------------------------------------------------------------------------
extern "C" void kernel_launch(void* const* d_in, const int* in_sizes, int n_in,
                              void* d_out, int out_size)
{
    const float* x          = (const float*)d_in[0];
    const float* w_qkv      = (const float*)d_in[1];
    const float* w_out      = (const float*)d_in[2];
    const float* b_out      = (const float*)d_in[3];
    const float* bias_table = (const float*)d_in[4];
    const float* gamma1     = (const float*)d_in[5];
    const float* beta1      = (const float*)d_in[6];
    const float* w_ff1      = (const float*)d_in[7];
    const float* b_ff1      = (const float*)d_in[8];
    const float* w_ff2      = (const float*)d_in[9];
    const float* b_ff2      = (const float*)d_in[10];
    const float* gamma2     = (const float*)d_in[11];
    const float* beta2      = (const float*)d_in[12];
    float* out = (float*)d_out;

    float *qkv, *ctx, *tmp, *x1, *hb;
    cudaGetSymbolAddress((void**)&qkv, g_qkv);
    cudaGetSymbolAddress((void**)&ctx, g_ctx);
    cudaGetSymbolAddress((void**)&tmp, g_tmp);
    cudaGetSymbolAddress((void**)&x1,  g_x1);
    cudaGetSymbolAddress((void**)&hb,  g_hb);

    cudaFuncSetAttribute(flash_attn_kernel,
                         cudaFuncAttributeMaxDynamicSharedMemorySize, ATTN_SMEM);

    const int M = Bsz*Lseq;  // 8192

    // 1. qkv = x @ w_qkv
    sgemm_kernel<0><<<dim3(3*Dmodel/128, M/128), 256>>>(
        x, w_qkv, qkv, M, 3*Dmodel, Dmodel, nullptr, nullptr);

    // 2. attention -> ctx
    flash_attn_kernel<<<dim3(Lseq/64, Bsz*Hheads), 256, ATTN_SMEM>>>(
        qkv, bias_table, ctx);

    // 3. tmp = ctx @ w_out + b_out + x (residual)
    sgemm_kernel<1><<<dim3(Dmodel/128, M/128), 256>>>(
        ctx, w_out, tmp, M, Dmodel, Dmodel, b_out, x);

    // 4. x1 = LN(tmp)
    ln_kernel<<<M, 256>>>(tmp, gamma1, beta1, x1);

    // 5. hb = GELU(x1 @ w_ff1 + b_ff1)
    sgemm_kernel<2><<<dim3(DffDim/128, M/128), 256>>>(
        x1, w_ff1, hb, M, DffDim, Dmodel, b_ff1, nullptr);

    // 6. tmp = hb @ w_ff2 + b_ff2 + x1 (residual)
    sgemm_kernel<1><<<dim3(Dmodel/128, M/128), 256>>>(
        hb, w_ff2, tmp, M, Dmodel, DffDim, b_ff2, x1);

    // 7. out = LN(tmp)
    ln_kernel<<<M, 256>>>(tmp, gamma2, beta2, out);
}

// round 3
// speedup vs baseline: 1.8154x; 1.8154x over previous
#include <cuda_runtime.h>
#include <math.h>
#include <stdint.h>

#define Bsz 4
#define Lseq 2048
#define Dmodel 1024
#define Hheads 16
#define DffDim 4096
#define MAXDIST 512
#define HDdim 64

// Scratch (allocation-free rule: __device__ globals)
__device__ float g_qkv[Bsz*Lseq*3*Dmodel];
__device__ float g_ctx[Bsz*Lseq*Dmodel];
__device__ float g_tmp[Bsz*Lseq*Dmodel];
__device__ float g_x1 [Bsz*Lseq*Dmodel];
__device__ float g_hb [Bsz*Lseq*DffDim];

// ---------------------------------------------------------------------------
// TF32 tensor-core GEMM: C[M,N] = A[M,K] @ B[K,N]
// 128x128x32 block tile, 8 warps (2 m x 4 n), warp tile 64x32,
// mma.sync m16n8k8 tf32, cp.async double buffering.
// EPI: 0 = none, 1 = +bias[n]+res, 2 = +bias[n] then exact GELU.
// ---------------------------------------------------------------------------
#define BM 128
#define BN 128
#define BK 32
#define AP 36    // A smem pitch (floats): bank = (4r+c)%32, conflict-free frags
#define BP 136   // B smem pitch (floats): bank = (8c+r)%32, conflict-free frags
#define ASZ (BM*AP)   // 4608 floats / buffer
#define BSZ (BK*BP)   // 4352 floats / buffer
#define GEMM_SMEM ((2*ASZ + 2*BSZ)*4)  // 71680 bytes

__device__ __forceinline__ uint32_t f2tf(float x) {
    uint32_t y;
    asm("cvt.rna.tf32.f32 %0, %1;" : "=r"(y) : "f"(x));
    return y;
}

template<int EPI>
__global__ __launch_bounds__(256, 2)
void tf32_gemm(const float* __restrict__ A, const float* __restrict__ B,
               float* __restrict__ C, int M, int N, int K,
               const float* __restrict__ bias, const float* __restrict__ res)
{
    extern __shared__ float sm[];
    float* sA = sm;            // [2][BM][AP]
    float* sB = sm + 2*ASZ;    // [2][BK][BP]
    const int tid = threadIdx.x;
    const int m0 = blockIdx.y * BM;
    const int n0 = blockIdx.x * BN;
    const int KT = K / BK;

    const int wid = tid >> 5, lane = tid & 31;
    const int wm = (wid & 1) * 64;     // warp m offset in tile
    const int wn = (wid >> 1) * 32;    // warp n offset in tile
    const int r  = lane >> 2;          // 0..7
    const int cc = lane & 3;           // 0..3

    auto loadA = [&](int kt, int buf) {
        const float* src = A + (size_t)m0 * K + kt * BK;
        float* dst = sA + buf * ASZ;
#pragma unroll
        for (int i = 0; i < 4; i++) {
            int idx = tid + i * 256;            // 1024 16B chunks
            int row = idx >> 3, c4 = (idx & 7) << 2;
            uint32_t sa = (uint32_t)__cvta_generic_to_shared(dst + row*AP + c4);
            asm volatile("cp.async.ca.shared.global [%0], [%1], 16;"
                         :: "r"(sa), "l"(src + (size_t)row * K + c4));
        }
    };
    auto loadB = [&](int kt, int buf) {
        const float* src = B + (size_t)kt * BK * N + n0;
        float* dst = sB + buf * BSZ;
#pragma unroll
        for (int i = 0; i < 4; i++) {
            int idx = tid + i * 256;
            int row = idx >> 5, c4 = (idx & 31) << 2;
            uint32_t sa = (uint32_t)__cvta_generic_to_shared(dst + row*BP + c4);
            asm volatile("cp.async.ca.shared.global [%0], [%1], 16;"
                         :: "r"(sa), "l"(src + (size_t)row * N + c4));
        }
    };

    float acc[4][4][4];
#pragma unroll
    for (int mi = 0; mi < 4; mi++)
#pragma unroll
        for (int ni = 0; ni < 4; ni++)
#pragma unroll
            for (int q = 0; q < 4; q++) acc[mi][ni][q] = 0.f;

    loadA(0, 0); loadB(0, 0);
    asm volatile("cp.async.commit_group;");

    for (int kt = 0; kt < KT; kt++) {
        if (kt + 1 < KT) {
            loadA(kt + 1, (kt + 1) & 1);
            loadB(kt + 1, (kt + 1) & 1);
            asm volatile("cp.async.commit_group;");
            asm volatile("cp.async.wait_group 1;");
        } else {
            asm volatile("cp.async.wait_group 0;");
        }
        __syncthreads();

        const float* aT = sA + (kt & 1) * ASZ;
        const float* bT = sB + (kt & 1) * BSZ;
#pragma unroll
        for (int ks = 0; ks < 4; ks++) {
            const int k = ks * 8;
            uint32_t af[4][4];
#pragma unroll
            for (int mi = 0; mi < 4; mi++) {
                int rw = wm + mi * 16 + r;
                af[mi][0] = f2tf(aT[rw      * AP + k + cc    ]);
                af[mi][1] = f2tf(aT[(rw + 8)* AP + k + cc    ]);
                af[mi][2] = f2tf(aT[rw      * AP + k + cc + 4]);
                af[mi][3] = f2tf(aT[(rw + 8)* AP + k + cc + 4]);
            }
            uint32_t bf[4][2];
#pragma unroll
            for (int ni = 0; ni < 4; ni++) {
                int col = wn + ni * 8 + r;
                bf[ni][0] = f2tf(bT[(k + cc    ) * BP + col]);
                bf[ni][1] = f2tf(bT[(k + cc + 4) * BP + col]);
            }
#pragma unroll
            for (int mi = 0; mi < 4; mi++)
#pragma unroll
                for (int ni = 0; ni < 4; ni++) {
                    asm volatile(
                        "mma.sync.aligned.m16n8k8.row.col.f32.tf32.tf32.f32 "
                        "{%0,%1,%2,%3}, {%4,%5,%6,%7}, {%8,%9}, {%0,%1,%2,%3};"
                        : "+f"(acc[mi][ni][0]), "+f"(acc[mi][ni][1]),
                          "+f"(acc[mi][ni][2]), "+f"(acc[mi][ni][3])
                        : "r"(af[mi][0]), "r"(af[mi][1]),
                          "r"(af[mi][2]), "r"(af[mi][3]),
                          "r"(bf[ni][0]), "r"(bf[ni][1]));
                }
        }
        __syncthreads();
    }

    // Epilogue. c0,c1 at (row, 2cc..2cc+1); c2,c3 at (row+8, same cols).
#pragma unroll
    for (int ni = 0; ni < 4; ni++) {
        const int col = n0 + wn + ni * 8 + 2 * cc;
        float b0 = 0.f, b1 = 0.f;
        if (EPI != 0) { b0 = bias[col]; b1 = bias[col + 1]; }
#pragma unroll
        for (int mi = 0; mi < 4; mi++) {
            const int row = m0 + wm + mi * 16 + r;
#pragma unroll
            for (int h = 0; h < 2; h++) {   // h=0: row, h=1: row+8
                const int rr = row + h * 8;
                float v0 = acc[mi][ni][2*h + 0];
                float v1 = acc[mi][ni][2*h + 1];
                if (EPI != 0) { v0 += b0; v1 += b1; }
                if (EPI == 1) {
                    v0 += res[(size_t)rr * N + col];
                    v1 += res[(size_t)rr * N + col + 1];
                }
                if (EPI == 2) {
                    v0 = v0 * normcdff(v0);
                    v1 = v1 * normcdff(v1);
                }
                *(float2*)&C[(size_t)rr * N + col] = make_float2(v0, v1);
            }
        }
    }
}

// ---------------------------------------------------------------------------
// Flash attention (fp32, unchanged from R2): one block per (64-row q-tile, b*h)
// ---------------------------------------------------------------------------
#define ATTN_SMEM (4*64*65*4)

__global__ __launch_bounds__(256)
void flash_attn_kernel(const float* __restrict__ qkv,
                       const float* __restrict__ bias_table,
                       float* __restrict__ ctx)
{
    extern __shared__ float smf[];
    float* Qs = smf;
    float* Ks = smf +   64*65;
    float* Vs = smf + 2*64*65;
    float* Ps = smf + 3*64*65;
    const int qt = blockIdx.x;
    const int bh = blockIdx.y;
    const int b = bh >> 4, h = bh & 15;
    const int tid = threadIdx.x;
    const int tx = tid & 15, ty = tid >> 4;
    const int q0 = qt * 64;
    const size_t rs = 3*Dmodel;
    const float* base = qkv + (size_t)(b*Lseq)*rs + h*HDdim;

    for (int idx = tid; idx < 64*16; idx += 256) {
        int r = idx >> 4, c4 = (idx & 15) << 2;
        float4 v = *(const float4*)(base + (size_t)(q0 + r)*rs + c4);
        Qs[r*65+c4+0] = v.x; Qs[r*65+c4+1] = v.y;
        Qs[r*65+c4+2] = v.z; Qs[r*65+c4+3] = v.w;
    }

    float m_i[4], l_i[4], O[4][4];
#pragma unroll
    for (int i = 0; i < 4; i++) {
        m_i[i] = -1e30f; l_i[i] = 0.f;
#pragma unroll
        for (int j = 0; j < 4; j++) O[i][j] = 0.f;
    }
    const float scale = 0.125f;
    __syncthreads();

    for (int kt = 0; kt < Lseq/64; kt++) {
        const int k0 = kt*64;
        for (int idx = tid; idx < 64*16; idx += 256) {
            int r = idx >> 4, c4 = (idx & 15) << 2;
            const float* kb = base + (size_t)(k0 + r)*rs + Dmodel + c4;
            float4 kv = *(const float4*)kb;
            Ks[r*65+c4+0] = kv.x; Ks[r*65+c4+1] = kv.y;
            Ks[r*65+c4+2] = kv.z; Ks[r*65+c4+3] = kv.w;
            float4 vv = *(const float4*)(kb + Dmodel);
            Vs[r*65+c4+0] = vv.x; Vs[r*65+c4+1] = vv.y;
            Vs[r*65+c4+2] = vv.z; Vs[r*65+c4+3] = vv.w;
        }
        __syncthreads();

        float s[4][4];
#pragma unroll
        for (int i = 0; i < 4; i++)
#pragma unroll
            for (int j = 0; j < 4; j++) s[i][j] = 0.f;
        for (int d = 0; d < 64; d++) {
            float a[4], bv[4];
#pragma unroll
            for (int i = 0; i < 4; i++) a[i]  = Qs[(ty*4+i)*65 + d];
#pragma unroll
            for (int j = 0; j < 4; j++) bv[j] = Ks[(tx*4+j)*65 + d];
#pragma unroll
            for (int i = 0; i < 4; i++)
#pragma unroll
                for (int j = 0; j < 4; j++)
                    s[i][j] = fmaf(a[i], bv[j], s[i][j]);
        }
#pragma unroll
        for (int i = 0; i < 4; i++) {
            int qg = q0 + ty*4 + i;
#pragma unroll
            for (int j = 0; j < 4; j++) {
                int kg = k0 + tx*4 + j;
                int rel = kg - qg + (MAXDIST-1);
                rel = min(max(rel, 0), 2*MAXDIST-2);
                s[i][j] = fmaf(s[i][j], scale, __ldg(&bias_table[rel*Hheads + h]));
            }
        }
#pragma unroll
        for (int i = 0; i < 4; i++) {
            float rmax = fmaxf(fmaxf(s[i][0], s[i][1]), fmaxf(s[i][2], s[i][3]));
#pragma unroll
            for (int o = 8; o >= 1; o >>= 1)
                rmax = fmaxf(rmax, __shfl_xor_sync(0xffffffffu, rmax, o));
            float mnew = fmaxf(m_i[i], rmax);
            float corr = __expf(m_i[i] - mnew);
            float rsum = 0.f;
#pragma unroll
            for (int j = 0; j < 4; j++) {
                float p = __expf(s[i][j] - mnew);
                Ps[(ty*4+i)*65 + tx*4 + j] = p;
                rsum += p;
            }
#pragma unroll
            for (int o = 8; o >= 1; o >>= 1)
                rsum += __shfl_xor_sync(0xffffffffu, rsum, o);
            l_i[i] = l_i[i]*corr + rsum;
            m_i[i] = mnew;
#pragma unroll
            for (int j = 0; j < 4; j++) O[i][j] *= corr;
        }
        __syncthreads();
        for (int k = 0; k < 64; k++) {
            float a[4], bv[4];
#pragma unroll
            for (int i = 0; i < 4; i++) a[i]  = Ps[(ty*4+i)*65 + k];
#pragma unroll
            for (int j = 0; j < 4; j++) bv[j] = Vs[k*65 + tx*4 + j];
#pragma unroll
            for (int i = 0; i < 4; i++)
#pragma unroll
                for (int j = 0; j < 4; j++)
                    O[i][j] = fmaf(a[i], bv[j], O[i][j]);
        }
        __syncthreads();
    }

#pragma unroll
    for (int i = 0; i < 4; i++) {
        float inv = 1.f / l_i[i];
        int qg = q0 + ty*4 + i;
        float* cp = ctx + (size_t)(b*Lseq + qg)*Dmodel + h*HDdim + tx*4;
#pragma unroll
        for (int j = 0; j < 4; j++) cp[j] = O[i][j]*inv;
    }
}

// ---------------------------------------------------------------------------
// LayerNorm over rows of 1024.
// ---------------------------------------------------------------------------
__global__ __launch_bounds__(256)
void ln_kernel(const float* __restrict__ in, const float* __restrict__ gamma,
               const float* __restrict__ beta, float* __restrict__ out)
{
    __shared__ float red[16];
    const int row = blockIdx.x;
    const int tid = threadIdx.x;
    float4 v = ((const float4*)(in + (size_t)row*Dmodel))[tid];
    float s  = v.x + v.y + v.z + v.w;
    float sq = v.x*v.x + v.y*v.y + v.z*v.z + v.w*v.w;
#pragma unroll
    for (int o = 16; o >= 1; o >>= 1) {
        s  += __shfl_xor_sync(0xffffffffu, s,  o);
        sq += __shfl_xor_sync(0xffffffffu, sq, o);
    }
    const int wid = tid >> 5, lane = tid & 31;
    if (lane == 0) { red[wid] = s; red[wid+8] = sq; }
    __syncthreads();
    if (tid < 32) {
        float s2 = (lane < 8) ? red[lane]   : 0.f;
        float q2 = (lane < 8) ? red[lane+8] : 0.f;
#pragma unroll
        for (int o = 4; o >= 1; o >>= 1) {
            s2 += __shfl_xor_sync(0xffffffffu, s2, o);
            q2 += __shfl_xor_sync(0xffffffffu, q2, o);
        }
        if (lane == 0) { red[0] = s2; red[1] = q2; }
    }
    __syncthreads();
    const float mu  = red[0] * (1.f/Dmodel);
    const float var = red[1] * (1.f/Dmodel) - mu*mu;
    const float inv = rsqrtf(var + 1e-5f);
    const float4 g  = ((const float4*)gamma)[tid];
    const float4 be = ((const float4*)beta)[tid];
    float4 o;
    o.x = (v.x - mu)*inv*g.x + be.x;
    o.y = (v.y - mu)*inv*g.y + be.y;
    o.z = (v.z - mu)*inv*g.z + be.z;
    o.w = (v.w - mu)*inv*g.w + be.w;
    ((float4*)(out + (size_t)row*Dmodel))[tid] = o;
}

// ---------------------------------------------------------------------------
extern "C" void kernel_launch(void* const* d_in, const int* in_sizes, int n_in,
                              void* d_out, int out_size)
{
    const float* x          = (const float*)d_in[0];
    const float* w_qkv      = (const float*)d_in[1];
    const float* w_out      = (const float*)d_in[2];
    const float* b_out      = (const float*)d_in[3];
    const float* bias_table = (const float*)d_in[4];
    const float* gamma1     = (const float*)d_in[5];
    const float* beta1      = (const float*)d_in[6];
    const float* w_ff1      = (const float*)d_in[7];
    const float* b_ff1      = (const float*)d_in[8];
    const float* w_ff2      = (const float*)d_in[9];
    const float* b_ff2      = (const float*)d_in[10];
    const float* gamma2     = (const float*)d_in[11];
    const float* beta2      = (const float*)d_in[12];
    float* out = (float*)d_out;

    float *qkv, *ctx, *tmp, *x1, *hb;
    cudaGetSymbolAddress((void**)&qkv, g_qkv);
    cudaGetSymbolAddress((void**)&ctx, g_ctx);
    cudaGetSymbolAddress((void**)&tmp, g_tmp);
    cudaGetSymbolAddress((void**)&x1,  g_x1);
    cudaGetSymbolAddress((void**)&hb,  g_hb);

    cudaFuncSetAttribute(flash_attn_kernel,
                         cudaFuncAttributeMaxDynamicSharedMemorySize, ATTN_SMEM);
    cudaFuncSetAttribute(tf32_gemm<0>,
                         cudaFuncAttributeMaxDynamicSharedMemorySize, GEMM_SMEM);
    cudaFuncSetAttribute(tf32_gemm<1>,
                         cudaFuncAttributeMaxDynamicSharedMemorySize, GEMM_SMEM);
    cudaFuncSetAttribute(tf32_gemm<2>,
                         cudaFuncAttributeMaxDynamicSharedMemorySize, GEMM_SMEM);

    const int M = Bsz*Lseq;  // 8192

    // 1. qkv = x @ w_qkv
    tf32_gemm<0><<<dim3(3*Dmodel/128, M/128), 256, GEMM_SMEM>>>(
        x, w_qkv, qkv, M, 3*Dmodel, Dmodel, nullptr, nullptr);

    // 2. attention -> ctx
    flash_attn_kernel<<<dim3(Lseq/64, Bsz*Hheads), 256, ATTN_SMEM>>>(
        qkv, bias_table, ctx);

    // 3. tmp = ctx @ w_out + b_out + x (residual)
    tf32_gemm<1><<<dim3(Dmodel/128, M/128), 256, GEMM_SMEM>>>(
        ctx, w_out, tmp, M, Dmodel, Dmodel, b_out, x);

    // 4. x1 = LN(tmp)
    ln_kernel<<<M, 256>>>(tmp, gamma1, beta1, x1);

    // 5. hb = GELU(x1 @ w_ff1 + b_ff1)
    tf32_gemm<2><<<dim3(DffDim/128, M/128), 256, GEMM_SMEM>>>(
        x1, w_ff1, hb, M, DffDim, Dmodel, b_ff1, nullptr);

    // 6. tmp = hb @ w_ff2 + b_ff2 + x1 (residual)
    tf32_gemm<1><<<dim3(Dmodel/128, M/128), 256, GEMM_SMEM>>>(
        hb, w_ff2, tmp, M, Dmodel, DffDim, b_ff2, x1);

    // 7. out = LN(tmp)
    ln_kernel<<<M, 256>>>(tmp, gamma2, beta2, out);
}

// round 4
// speedup vs baseline: 3.5599x; 1.9609x over previous
#include <cuda_runtime.h>
#include <math.h>
#include <stdint.h>

#define Bsz 4
#define Lseq 2048
#define Dmodel 1024
#define Hheads 16
#define DffDim 4096
#define MAXDIST 512
#define HDdim 64

// Scratch (allocation-free rule: __device__ globals)
__device__ float g_qkv[Bsz*Lseq*3*Dmodel];
__device__ float g_ctx[Bsz*Lseq*Dmodel];
__device__ float g_tmp[Bsz*Lseq*Dmodel];
__device__ float g_x1 [Bsz*Lseq*Dmodel];
__device__ float g_hb [Bsz*Lseq*DffDim];

__device__ __forceinline__ uint32_t f2tf(float x) {
    uint32_t y;
    asm("cvt.rna.tf32.f32 %0, %1;" : "=r"(y) : "f"(x));
    return y;
}

__device__ __forceinline__ void mma_tf32(float* c, const uint32_t* a,
                                         uint32_t b0, uint32_t b1) {
    asm volatile(
        "mma.sync.aligned.m16n8k8.row.col.f32.tf32.tf32.f32 "
        "{%0,%1,%2,%3}, {%4,%5,%6,%7}, {%8,%9}, {%0,%1,%2,%3};"
        : "+f"(c[0]), "+f"(c[1]), "+f"(c[2]), "+f"(c[3])
        : "r"(a[0]), "r"(a[1]), "r"(a[2]), "r"(a[3]), "r"(b0), "r"(b1));
}

// ---------------------------------------------------------------------------
// TF32 tensor-core GEMM (unchanged from R3): 128x128x32, 8 warps, cp.async.
// ---------------------------------------------------------------------------
#define BM 128
#define BN 128
#define BK 32
#define AP 36
#define BP 136
#define ASZ (BM*AP)
#define BSZ (BK*BP)
#define GEMM_SMEM ((2*ASZ + 2*BSZ)*4)

template<int EPI>
__global__ __launch_bounds__(256, 2)
void tf32_gemm(const float* __restrict__ A, const float* __restrict__ B,
               float* __restrict__ C, int M, int N, int K,
               const float* __restrict__ bias, const float* __restrict__ res)
{
    extern __shared__ float sm[];
    float* sA = sm;
    float* sB = sm + 2*ASZ;
    const int tid = threadIdx.x;
    const int m0 = blockIdx.y * BM;
    const int n0 = blockIdx.x * BN;
    const int KT = K / BK;

    const int wid = tid >> 5, lane = tid & 31;
    const int wm = (wid & 1) * 64;
    const int wn = (wid >> 1) * 32;
    const int r  = lane >> 2;
    const int cc = lane & 3;

    auto loadA = [&](int kt, int buf) {
        const float* src = A + (size_t)m0 * K + kt * BK;
        float* dst = sA + buf * ASZ;
#pragma unroll
        for (int i = 0; i < 4; i++) {
            int idx = tid + i * 256;
            int row = idx >> 3, c4 = (idx & 7) << 2;
            uint32_t sa = (uint32_t)__cvta_generic_to_shared(dst + row*AP + c4);
            asm volatile("cp.async.ca.shared.global [%0], [%1], 16;"
                         :: "r"(sa), "l"(src + (size_t)row * K + c4));
        }
    };
    auto loadB = [&](int kt, int buf) {
        const float* src = B + (size_t)kt * BK * N + n0;
        float* dst = sB + buf * BSZ;
#pragma unroll
        for (int i = 0; i < 4; i++) {
            int idx = tid + i * 256;
            int row = idx >> 5, c4 = (idx & 31) << 2;
            uint32_t sa = (uint32_t)__cvta_generic_to_shared(dst + row*BP + c4);
            asm volatile("cp.async.ca.shared.global [%0], [%1], 16;"
                         :: "r"(sa), "l"(src + (size_t)row * N + c4));
        }
    };

    float acc[4][4][4];
#pragma unroll
    for (int mi = 0; mi < 4; mi++)
#pragma unroll
        for (int ni = 0; ni < 4; ni++)
#pragma unroll
            for (int q = 0; q < 4; q++) acc[mi][ni][q] = 0.f;

    loadA(0, 0); loadB(0, 0);
    asm volatile("cp.async.commit_group;");

    for (int kt = 0; kt < KT; kt++) {
        if (kt + 1 < KT) {
            loadA(kt + 1, (kt + 1) & 1);
            loadB(kt + 1, (kt + 1) & 1);
            asm volatile("cp.async.commit_group;");
            asm volatile("cp.async.wait_group 1;");
        } else {
            asm volatile("cp.async.wait_group 0;");
        }
        __syncthreads();

        const float* aT = sA + (kt & 1) * ASZ;
        const float* bT = sB + (kt & 1) * BSZ;
#pragma unroll
        for (int ks = 0; ks < 4; ks++) {
            const int k = ks * 8;
            uint32_t af[4][4];
#pragma unroll
            for (int mi = 0; mi < 4; mi++) {
                int rw = wm + mi * 16 + r;
                af[mi][0] = f2tf(aT[rw      * AP + k + cc    ]);
                af[mi][1] = f2tf(aT[(rw + 8)* AP + k + cc    ]);
                af[mi][2] = f2tf(aT[rw      * AP + k + cc + 4]);
                af[mi][3] = f2tf(aT[(rw + 8)* AP + k + cc + 4]);
            }
            uint32_t bf[4][2];
#pragma unroll
            for (int ni = 0; ni < 4; ni++) {
                int col = wn + ni * 8 + r;
                bf[ni][0] = f2tf(bT[(k + cc    ) * BP + col]);
                bf[ni][1] = f2tf(bT[(k + cc + 4) * BP + col]);
            }
#pragma unroll
            for (int mi = 0; mi < 4; mi++)
#pragma unroll
                for (int ni = 0; ni < 4; ni++)
                    mma_tf32(acc[mi][ni], af[mi], bf[ni][0], bf[ni][1]);
        }
        __syncthreads();
    }

#pragma unroll
    for (int ni = 0; ni < 4; ni++) {
        const int col = n0 + wn + ni * 8 + 2 * cc;
        float b0 = 0.f, b1 = 0.f;
        if (EPI != 0) { b0 = bias[col]; b1 = bias[col + 1]; }
#pragma unroll
        for (int mi = 0; mi < 4; mi++) {
            const int row = m0 + wm + mi * 16 + r;
#pragma unroll
            for (int h = 0; h < 2; h++) {
                const int rr = row + h * 8;
                float v0 = acc[mi][ni][2*h + 0];
                float v1 = acc[mi][ni][2*h + 1];
                if (EPI != 0) { v0 += b0; v1 += b1; }
                if (EPI == 1) {
                    v0 += res[(size_t)rr * N + col];
                    v1 += res[(size_t)rr * N + col + 1];
                }
                if (EPI == 2) {
                    v0 = v0 * normcdff(v0);
                    v1 = v1 * normcdff(v1);
                }
                *(float2*)&C[(size_t)rr * N + col] = make_float2(v0, v1);
            }
        }
    }
}

// ---------------------------------------------------------------------------
// TF32 tensor-core flash attention.
// Block: 128 threads (4 warps), 64-row Q tile, 64-key KV tiles.
// Warp w owns S rows [16w, 16w+16); per kv-tile: S = Q K^T via 8x8 mma grid,
// online softmax on accum layout (4-lane row reduce), P via smem, O += P V.
// ---------------------------------------------------------------------------
#define AQP 68   // Q smem pitch: frag bank = 4r+cc (conflict-free)
#define AKP 68   // K smem pitch (row-indexed by key): bank = 4n+cc
#define AVP 72   // V smem pitch (row-indexed by key): bank = 8cc+n
#define APP 68   // P smem pitch (read as A-frags)
#define FA_SMEM ((64*AQP + 64*AKP + 64*AVP + 64*APP + 1024)*4)

__global__ __launch_bounds__(128, 2)
void flash_attn_tc(const float* __restrict__ qkv,
                   const float* __restrict__ bias_table,
                   float* __restrict__ ctx)
{
    extern __shared__ float sm[];
    float* Qs = sm;
    float* Ks = Qs + 64*AQP;
    float* Vs = Ks + 64*AKP;
    float* Ps = Vs + 64*AVP;
    float* Bias = Ps + 64*APP;   // 1023 floats used

    const int qt = blockIdx.x;
    const int bh = blockIdx.y;
    const int b = bh >> 4, h = bh & 15;
    const int tid = threadIdx.x;
    const int wid = tid >> 5, lane = tid & 31;
    const int r = lane >> 2, cc = lane & 3;
    const int q0 = qt * 64;
    const int wr = wid * 16;          // warp's S row offset
    const size_t rs = 3*Dmodel;
    const float* base = qkv + (size_t)(b*Lseq)*rs + h*HDdim;

    // Bias row for this head into smem
    for (int i = tid; i < 2*MAXDIST-1; i += 128)
        Bias[i] = bias_table[(size_t)i*Hheads + h];

    // Q tile via cp.async
#pragma unroll
    for (int i = 0; i < 8; i++) {
        int idx = tid + i*128;
        int row = idx >> 4, c4 = (idx & 15) << 2;
        uint32_t sa = (uint32_t)__cvta_generic_to_shared(Qs + row*AQP + c4);
        asm volatile("cp.async.ca.shared.global [%0], [%1], 16;"
                     :: "r"(sa), "l"(base + (size_t)(q0 + row)*rs + c4));
    }
    asm volatile("cp.async.commit_group;");
    asm volatile("cp.async.wait_group 0;");
    __syncthreads();

    // Q fragments in registers (m16 x k64)
    uint32_t qf[8][4];
#pragma unroll
    for (int ks = 0; ks < 8; ks++) {
        const int k = ks*8;
        qf[ks][0] = f2tf(Qs[(wr + r    )*AQP + k + cc    ]);
        qf[ks][1] = f2tf(Qs[(wr + r + 8)*AQP + k + cc    ]);
        qf[ks][2] = f2tf(Qs[(wr + r    )*AQP + k + cc + 4]);
        qf[ks][3] = f2tf(Qs[(wr + r + 8)*AQP + k + cc + 4]);
    }

    float oacc[8][4];
#pragma unroll
    for (int nt = 0; nt < 8; nt++)
#pragma unroll
        for (int q = 0; q < 4; q++) oacc[nt][q] = 0.f;
    float m0v = -1e30f, m1v = -1e30f, l0 = 0.f, l1 = 0.f;
    const float scale = 0.125f;
    const int qg0 = q0 + wr + r, qg1 = qg0 + 8;

    for (int kt = 0; kt < Lseq/64; kt++) {
        const int k0 = kt*64;
        // Load K,V tiles (64x64 each)
#pragma unroll
        for (int i = 0; i < 8; i++) {
            int idx = tid + i*128;
            int row = idx >> 4, c4 = (idx & 15) << 2;
            const float* gk = base + (size_t)(k0 + row)*rs + Dmodel + c4;
            uint32_t sk = (uint32_t)__cvta_generic_to_shared(Ks + row*AKP + c4);
            asm volatile("cp.async.ca.shared.global [%0], [%1], 16;"
                         :: "r"(sk), "l"(gk));
            uint32_t sv = (uint32_t)__cvta_generic_to_shared(Vs + row*AVP + c4);
            asm volatile("cp.async.ca.shared.global [%0], [%1], 16;"
                         :: "r"(sv), "l"(gk + Dmodel));
        }
        asm volatile("cp.async.commit_group;");
        asm volatile("cp.async.wait_group 0;");
        __syncthreads();

        // S = Q @ K^T : 8 n-tiles x 8 k-steps
        float sacc[8][4];
#pragma unroll
        for (int nt = 0; nt < 8; nt++)
#pragma unroll
            for (int q = 0; q < 4; q++) sacc[nt][q] = 0.f;
#pragma unroll
        for (int ks = 0; ks < 8; ks++) {
            const int k = ks*8;
#pragma unroll
            for (int nt = 0; nt < 8; nt++) {
                const float* kp = Ks + (nt*8 + r)*AKP + k + cc;
                uint32_t b0 = f2tf(kp[0]);
                uint32_t b1 = f2tf(kp[4]);
                mma_tf32(sacc[nt], qf[ks], b0, b1);
            }
        }

        // scale + bias + online softmax
        float rmax0 = -1e30f, rmax1 = -1e30f;
#pragma unroll
        for (int nt = 0; nt < 8; nt++) {
            const int kg = k0 + nt*8 + 2*cc;
            int i00 = min(max(kg     - qg0 + (MAXDIST-1), 0), 2*MAXDIST-2);
            int i01 = min(max(kg + 1 - qg0 + (MAXDIST-1), 0), 2*MAXDIST-2);
            int i10 = min(max(kg     - qg1 + (MAXDIST-1), 0), 2*MAXDIST-2);
            int i11 = min(max(kg + 1 - qg1 + (MAXDIST-1), 0), 2*MAXDIST-2);
            sacc[nt][0] = fmaf(sacc[nt][0], scale, Bias[i00]);
            sacc[nt][1] = fmaf(sacc[nt][1], scale, Bias[i01]);
            sacc[nt][2] = fmaf(sacc[nt][2], scale, Bias[i10]);
            sacc[nt][3] = fmaf(sacc[nt][3], scale, Bias[i11]);
            rmax0 = fmaxf(rmax0, fmaxf(sacc[nt][0], sacc[nt][1]));
            rmax1 = fmaxf(rmax1, fmaxf(sacc[nt][2], sacc[nt][3]));
        }
#pragma unroll
        for (int o = 1; o <= 2; o <<= 1) {
            rmax0 = fmaxf(rmax0, __shfl_xor_sync(0xffffffffu, rmax0, o));
            rmax1 = fmaxf(rmax1, __shfl_xor_sync(0xffffffffu, rmax1, o));
        }
        const float mn0 = fmaxf(m0v, rmax0);
        const float mn1 = fmaxf(m1v, rmax1);
        const float corr0 = __expf(m0v - mn0);
        const float corr1 = __expf(m1v - mn1);
        m0v = mn0; m1v = mn1;

        float rsum0 = 0.f, rsum1 = 0.f;
#pragma unroll
        for (int nt = 0; nt < 8; nt++) {
            float p00 = __expf(sacc[nt][0] - mn0);
            float p01 = __expf(sacc[nt][1] - mn0);
            float p10 = __expf(sacc[nt][2] - mn1);
            float p11 = __expf(sacc[nt][3] - mn1);
            rsum0 += p00 + p01;
            rsum1 += p10 + p11;
            *(float2*)&Ps[(wr + r    )*APP + nt*8 + 2*cc] = make_float2(p00, p01);
            *(float2*)&Ps[(wr + r + 8)*APP + nt*8 + 2*cc] = make_float2(p10, p11);
        }
#pragma unroll
        for (int o = 1; o <= 2; o <<= 1) {
            rsum0 += __shfl_xor_sync(0xffffffffu, rsum0, o);
            rsum1 += __shfl_xor_sync(0xffffffffu, rsum1, o);
        }
        l0 = l0*corr0 + rsum0;
        l1 = l1*corr1 + rsum1;
#pragma unroll
        for (int nt = 0; nt < 8; nt++) {
            oacc[nt][0] *= corr0; oacc[nt][1] *= corr0;
            oacc[nt][2] *= corr1; oacc[nt][3] *= corr1;
        }
        __syncthreads();  // P visible to whole warp-group pattern; K reads done

        // O += P @ V : k over 64 keys, n over 64 dims
#pragma unroll
        for (int ks = 0; ks < 8; ks++) {
            const int k = ks*8;
            uint32_t pf[4];
            pf[0] = f2tf(Ps[(wr + r    )*APP + k + cc    ]);
            pf[1] = f2tf(Ps[(wr + r + 8)*APP + k + cc    ]);
            pf[2] = f2tf(Ps[(wr + r    )*APP + k + cc + 4]);
            pf[3] = f2tf(Ps[(wr + r + 8)*APP + k + cc + 4]);
#pragma unroll
            for (int nt = 0; nt < 8; nt++) {
                uint32_t b0 = f2tf(Vs[(k + cc    )*AVP + nt*8 + r]);
                uint32_t b1 = f2tf(Vs[(k + cc + 4)*AVP + nt*8 + r]);
                mma_tf32(oacc[nt], pf, b0, b1);
            }
        }
        __syncthreads();  // done reading Vs/Ps before next tile overwrites
    }

    const float inv0 = 1.f / l0;
    const float inv1 = 1.f / l1;
    float* c0p = ctx + (size_t)(b*Lseq + qg0)*Dmodel + h*HDdim;
    float* c1p = ctx + (size_t)(b*Lseq + qg1)*Dmodel + h*HDdim;
#pragma unroll
    for (int nt = 0; nt < 8; nt++) {
        const int col = nt*8 + 2*cc;
        *(float2*)&c0p[col] = make_float2(oacc[nt][0]*inv0, oacc[nt][1]*inv0);
        *(float2*)&c1p[col] = make_float2(oacc[nt][2]*inv1, oacc[nt][3]*inv1);
    }
}

// ---------------------------------------------------------------------------
// LayerNorm over rows of 1024.
// ---------------------------------------------------------------------------
__global__ __launch_bounds__(256)
void ln_kernel(const float* __restrict__ in, const float* __restrict__ gamma,
               const float* __restrict__ beta, float* __restrict__ out)
{
    __shared__ float red[16];
    const int row = blockIdx.x;
    const int tid = threadIdx.x;
    float4 v = ((const float4*)(in + (size_t)row*Dmodel))[tid];
    float s  = v.x + v.y + v.z + v.w;
    float sq = v.x*v.x + v.y*v.y + v.z*v.z + v.w*v.w;
#pragma unroll
    for (int o = 16; o >= 1; o >>= 1) {
        s  += __shfl_xor_sync(0xffffffffu, s,  o);
        sq += __shfl_xor_sync(0xffffffffu, sq, o);
    }
    const int wid = tid >> 5, lane = tid & 31;
    if (lane == 0) { red[wid] = s; red[wid+8] = sq; }
    __syncthreads();
    if (tid < 32) {
        float s2 = (lane < 8) ? red[lane]   : 0.f;
        float q2 = (lane < 8) ? red[lane+8] : 0.f;
#pragma unroll
        for (int o = 4; o >= 1; o >>= 1) {
            s2 += __shfl_xor_sync(0xffffffffu, s2, o);
            q2 += __shfl_xor_sync(0xffffffffu, q2, o);
        }
        if (lane == 0) { red[0] = s2; red[1] = q2; }
    }
    __syncthreads();
    const float mu  = red[0] * (1.f/Dmodel);
    const float var = red[1] * (1.f/Dmodel) - mu*mu;
    const float inv = rsqrtf(var + 1e-5f);
    const float4 g  = ((const float4*)gamma)[tid];
    const float4 be = ((const float4*)beta)[tid];
    float4 o;
    o.x = (v.x - mu)*inv*g.x + be.x;
    o.y = (v.y - mu)*inv*g.y + be.y;
    o.z = (v.z - mu)*inv*g.z + be.z;
    o.w = (v.w - mu)*inv*g.w + be.w;
    ((float4*)(out + (size_t)row*Dmodel))[tid] = o;
}

// ---------------------------------------------------------------------------
extern "C" void kernel_launch(void* const* d_in, const int* in_sizes, int n_in,
                              void* d_out, int out_size)
{
    const float* x          = (const float*)d_in[0];
    const float* w_qkv      = (const float*)d_in[1];
    const float* w_out      = (const float*)d_in[2];
    const float* b_out      = (const float*)d_in[3];
    const float* bias_table = (const float*)d_in[4];
    const float* gamma1     = (const float*)d_in[5];
    const float* beta1      = (const float*)d_in[6];
    const float* w_ff1      = (const float*)d_in[7];
    const float* b_ff1      = (const float*)d_in[8];
    const float* w_ff2      = (const float*)d_in[9];
    const float* b_ff2      = (const float*)d_in[10];
    const float* gamma2     = (const float*)d_in[11];
    const float* beta2      = (const float*)d_in[12];
    float* out = (float*)d_out;

    float *qkv, *ctx, *tmp, *x1, *hb;
    cudaGetSymbolAddress((void**)&qkv, g_qkv);
    cudaGetSymbolAddress((void**)&ctx, g_ctx);
    cudaGetSymbolAddress((void**)&tmp, g_tmp);
    cudaGetSymbolAddress((void**)&x1,  g_x1);
    cudaGetSymbolAddress((void**)&hb,  g_hb);

    cudaFuncSetAttribute(flash_attn_tc,
                         cudaFuncAttributeMaxDynamicSharedMemorySize, FA_SMEM);
    cudaFuncSetAttribute(tf32_gemm<0>,
                         cudaFuncAttributeMaxDynamicSharedMemorySize, GEMM_SMEM);
    cudaFuncSetAttribute(tf32_gemm<1>,
                         cudaFuncAttributeMaxDynamicSharedMemorySize, GEMM_SMEM);
    cudaFuncSetAttribute(tf32_gemm<2>,
                         cudaFuncAttributeMaxDynamicSharedMemorySize, GEMM_SMEM);

    const int M = Bsz*Lseq;  // 8192

    // 1. qkv = x @ w_qkv
    tf32_gemm<0><<<dim3(3*Dmodel/128, M/128), 256, GEMM_SMEM>>>(
        x, w_qkv, qkv, M, 3*Dmodel, Dmodel, nullptr, nullptr);

    // 2. attention -> ctx (tensor cores)
    flash_attn_tc<<<dim3(Lseq/64, Bsz*Hheads), 128, FA_SMEM>>>(
        qkv, bias_table, ctx);

    // 3. tmp = ctx @ w_out + b_out + x (residual)
    tf32_gemm<1><<<dim3(Dmodel/128, M/128), 256, GEMM_SMEM>>>(
        ctx, w_out, tmp, M, Dmodel, Dmodel, b_out, x);

    // 4. x1 = LN(tmp)
    ln_kernel<<<M, 256>>>(tmp, gamma1, beta1, x1);

    // 5. hb = GELU(x1 @ w_ff1 + b_ff1)
    tf32_gemm<2><<<dim3(DffDim/128, M/128), 256, GEMM_SMEM>>>(
        x1, w_ff1, hb, M, DffDim, Dmodel, b_ff1, nullptr);

    // 6. tmp = hb @ w_ff2 + b_ff2 + x1 (residual)
    tf32_gemm<1><<<dim3(Dmodel/128, M/128), 256, GEMM_SMEM>>>(
        hb, w_ff2, tmp, M, Dmodel, DffDim, b_ff2, x1);

    // 7. out = LN(tmp)
    ln_kernel<<<M, 256>>>(tmp, gamma2, beta2, out);
}

// round 7
// speedup vs baseline: 7.1657x; 2.0129x over previous
#include <cuda_runtime.h>
#include <cuda_fp16.h>
#include <math.h>
#include <stdint.h>

#define Bsz 4
#define Lseq 2048
#define Dmodel 1024
#define Hheads 16
#define DffDim 4096
#define MAXDIST 512
#define HDdim 64
#define Mrows (Bsz*Lseq)

// Scratch (allocation-free rule: __device__ globals)
__device__ __half h_x   [Mrows*Dmodel];
__device__ __half h_wqkv[Dmodel*3*Dmodel];
__device__ __half h_wout[Dmodel*Dmodel];
__device__ __half h_wff1[Dmodel*DffDim];
__device__ __half h_wff2[DffDim*Dmodel];
__device__ __half h_qkv [Mrows*3*Dmodel];
__device__ __half h_ctx [Mrows*Dmodel];
__device__ __half h_x1  [Mrows*Dmodel];
__device__ __half h_hb  [Mrows*DffDim];
__device__ float  g_tmp [Mrows*Dmodel];
__device__ float  g_x1f [Mrows*Dmodel];

// ---------------------------------------------------------------------------
__device__ __forceinline__ uint32_t s2u(const void* p) {
    uint32_t a;
    asm("{ .reg .u64 t; cvta.to.shared.u64 t, %1; cvt.u32.u64 %0, t; }"
        : "=r"(a) : "l"(p));
    return a;
}
__device__ __forceinline__ void ldsm4(uint32_t* r, uint32_t a) {
    asm volatile("ldmatrix.sync.aligned.m8n8.x4.shared.b16 {%0,%1,%2,%3}, [%4];"
                 : "=r"(r[0]), "=r"(r[1]), "=r"(r[2]), "=r"(r[3]) : "r"(a));
}
__device__ __forceinline__ void ldsm4t(uint32_t* r, uint32_t a) {
    asm volatile("ldmatrix.sync.aligned.m8n8.x4.trans.shared.b16 {%0,%1,%2,%3}, [%4];"
                 : "=r"(r[0]), "=r"(r[1]), "=r"(r[2]), "=r"(r[3]) : "r"(a));
}
__device__ __forceinline__ void mma16(float* c, const uint32_t* a,
                                      uint32_t b0, uint32_t b1) {
    asm volatile(
        "mma.sync.aligned.m16n8k16.row.col.f32.f16.f16.f32 "
        "{%0,%1,%2,%3}, {%4,%5,%6,%7}, {%8,%9}, {%0,%1,%2,%3};"
        : "+f"(c[0]), "+f"(c[1]), "+f"(c[2]), "+f"(c[3])
        : "r"(a[0]), "r"(a[1]), "r"(a[2]), "r"(a[3]), "r"(b0), "r"(b1));
}
#define CPA16(dst, src) \
    asm volatile("cp.async.ca.shared.global [%0], [%1], 16;" :: "r"(dst), "l"(src))
#define CPA_COMMIT() asm volatile("cp.async.commit_group;")

// ---------------------------------------------------------------------------
// fp32 -> fp16 conversion (vectorized)
// ---------------------------------------------------------------------------
__global__ void cvt_f16(const float4* __restrict__ in, __half2* __restrict__ out,
                        int n4)
{
    int i = blockIdx.x*256 + threadIdx.x;
    if (i < n4) {
        float4 v = in[i];
        out[2*i  ] = __floats2half2_rn(v.x, v.y);
        out[2*i+1] = __floats2half2_rn(v.z, v.w);
    }
}

// ---------------------------------------------------------------------------
// fp16 tensor-core GEMM: C[M,N] = A[M,K] @ B[K,N] (both fp16, fp32 accum).
// 128x128x64 tile, 8 warps (2m x 4n), warp 64x32, ldmatrix + m16n8k16,
// 3-stage cp.async. Smem: XOR-swizzled 8-half chunks (conflict-free LDSM).
// EPI: 0 none, 1 +bias[n]+res[m,n] (fp32), 2 +bias then exact GELU.
// OUTH: 1 -> write fp16 to Ch, 0 -> fp32 to Cf.
// ---------------------------------------------------------------------------
#define G_SMEM (3*32768)

template<int EPI, int OUTH>
__global__ __launch_bounds__(256, 2)
void gemm_f16(const __half* __restrict__ A, const __half* __restrict__ B,
              float* __restrict__ Cf, __half* __restrict__ Ch,
              int M, int N, int K,
              const float* __restrict__ bias, const float* __restrict__ res)
{
    extern __shared__ char smem[];
    const uint32_t sb = s2u(smem);
    const int tid = threadIdx.x, wid = tid >> 5, lane = tid & 31;
    const int m0 = blockIdx.y*128, n0 = blockIdx.x*128;
    const int KT = K >> 6;
    const int wm = (wid & 1)*64, wn = (wid >> 1)*32;
    const int r = lane >> 2, cc = lane & 3;
    const int l7 = lane & 7, l15 = lane & 15, lh = lane >> 4;

    auto loadAB = [&](int kt, int s) {
        const uint32_t stA = sb + s*32768;
        const uint32_t stB = stA + 16384;
#pragma unroll
        for (int i = 0; i < 4; i++) {           // A: 128 rows x 8 chunks
            int idx = tid + i*256;
            int row = idx >> 3, ch = idx & 7;
            uint32_t dst = stA + row*128 + ((ch ^ (row & 7)) << 4);
            CPA16(dst, A + (size_t)(m0 + row)*K + kt*64 + ch*8);
        }
#pragma unroll
        for (int i = 0; i < 4; i++) {           // B: 64 k-rows x 16 chunks
            int idx = tid + i*256;
            int k = idx >> 4, ch = idx & 15;
            uint32_t dst = stB + k*256 + ((ch ^ (k & 7)) << 4);
            CPA16(dst, B + (size_t)(kt*64 + k)*N + n0 + ch*8);
        }
    };

    float acc[4][4][4];
#pragma unroll
    for (int mi = 0; mi < 4; mi++)
#pragma unroll
        for (int ni = 0; ni < 4; ni++)
#pragma unroll
            for (int q = 0; q < 4; q++) acc[mi][ni][q] = 0.f;

    loadAB(0, 0); CPA_COMMIT();
    loadAB(1, 1); CPA_COMMIT();

    for (int kt = 0; kt < KT; kt++) {
        const int s = kt % 3;
        if (kt + 2 < KT) {
            loadAB(kt + 2, (kt + 2) % 3);
            CPA_COMMIT();
            asm volatile("cp.async.wait_group 2;");
        } else if (kt + 1 < KT) {
            asm volatile("cp.async.wait_group 1;");
        } else {
            asm volatile("cp.async.wait_group 0;");
        }
        __syncthreads();

        const uint32_t stA = sb + s*32768;
        const uint32_t stB = stA + 16384;
#pragma unroll
        for (int ks = 0; ks < 4; ks++) {
            uint32_t af[4][4];
#pragma unroll
            for (int mi = 0; mi < 4; mi++) {
                int row = wm + mi*16 + l15;
                ldsm4(af[mi], stA + row*128 + (((ks*2 + lh) ^ l7) << 4));
            }
#pragma unroll
            for (int p = 0; p < 2; p++) {
                int kk = ks*16 + l15;
                int cb = (wn >> 3) + p*2 + lh;
                uint32_t bf[4];
                ldsm4t(bf, stB + kk*256 + ((cb ^ l7) << 4));
#pragma unroll
                for (int mi = 0; mi < 4; mi++) {
                    mma16(acc[mi][2*p  ], af[mi], bf[0], bf[1]);
                    mma16(acc[mi][2*p+1], af[mi], bf[2], bf[3]);
                }
            }
        }
        __syncthreads();
    }

    // Epilogue
#pragma unroll
    for (int ni = 0; ni < 4; ni++) {
        const int col = n0 + wn + ni*8 + 2*cc;
        float b0 = 0.f, b1 = 0.f;
        if (EPI != 0) { b0 = bias[col]; b1 = bias[col + 1]; }
#pragma unroll
        for (int mi = 0; mi < 4; mi++) {
#pragma unroll
            for (int hh = 0; hh < 2; hh++) {
                const int rr = m0 + wm + mi*16 + r + hh*8;
                float v0 = acc[mi][ni][2*hh    ];
                float v1 = acc[mi][ni][2*hh + 1];
                if (EPI != 0) { v0 += b0; v1 += b1; }
                if (EPI == 1) {
                    v0 += res[(size_t)rr*N + col];
                    v1 += res[(size_t)rr*N + col + 1];
                }
                if (EPI == 2) {
                    v0 = v0 * normcdff(v0);
                    v1 = v1 * normcdff(v1);
                }
                if (OUTH)
                    *(__half2*)&Ch[(size_t)rr*N + col] = __floats2half2_rn(v0, v1);
                else
                    *(float2*)&Cf[(size_t)rr*N + col] = make_float2(v0, v1);
            }
        }
    }
}

// ---------------------------------------------------------------------------
// fp16 flash attention: 128 thr / 4 warps, 64-row Q tile, 64-key KV tiles,
// ldmatrix + m16n8k16, fp32 online softmax, fp16 P via smem, fp16 ctx out.
// ---------------------------------------------------------------------------
__global__ __launch_bounds__(128, 4)
void flash_attn_f16(const __half* __restrict__ qkv,
                    const float* __restrict__ bias_table,
                    __half* __restrict__ ctx)
{
    __shared__ __half Qs[64*64], Ks[64*64], Vs[64*64], Ps[64*64];
    __shared__ float Bias[1024];

    const int qt = blockIdx.x, bh = blockIdx.y;
    const int b = bh >> 4, h = bh & 15;
    const int tid = threadIdx.x;
    const int wid = tid >> 5, lane = tid & 31;
    const int r = lane >> 2, cc = lane & 3;
    const int l7 = lane & 7, l15 = lane & 15, lh = lane >> 4;
    const int q0 = qt*64, wr = wid*16;
    const size_t rs = 3*Dmodel;
    const __half* base = qkv + (size_t)(b*Lseq)*rs + h*HDdim;

    const uint32_t Qb = s2u(Qs), Kb = s2u(Ks), Vb = s2u(Vs), Pb = s2u(Ps);

    for (int i = tid; i < 2*MAXDIST-1; i += 128)
        Bias[i] = __ldg(&bias_table[(size_t)i*Hheads + h]);

#pragma unroll
    for (int i = 0; i < 4; i++) {               // Q: 64 rows x 8 chunks
        int idx = tid + i*128;
        int row = idx >> 3, ch = idx & 7;
        CPA16(Qb + row*128 + ((ch ^ (row & 7)) << 4),
              base + (size_t)(q0 + row)*rs + ch*8);
    }
    CPA_COMMIT();
    asm volatile("cp.async.wait_group 0;");
    __syncthreads();

    uint32_t qa[4][4];
#pragma unroll
    for (int ks = 0; ks < 4; ks++) {
        int row = wr + l15;
        ldsm4(qa[ks], Qb + row*128 + (((ks*2 + lh) ^ l7) << 4));
    }

    float oacc[8][4];
#pragma unroll
    for (int nt = 0; nt < 8; nt++)
#pragma unroll
        for (int q = 0; q < 4; q++) oacc[nt][q] = 0.f;
    float m0v = -1e30f, m1v = -1e30f, l0 = 0.f, l1 = 0.f;
    const float scale = 0.125f;
    const int qg0 = q0 + wr + r, qg1 = qg0 + 8;

    for (int kt = 0; kt < Lseq/64; kt++) {
        const int k0 = kt*64;
#pragma unroll
        for (int i = 0; i < 4; i++) {           // K+V: 64 rows x 8 chunks each
            int idx = tid + i*128;
            int row = idx >> 3, ch = idx & 7;
            const __half* gk = base + (size_t)(k0 + row)*rs + Dmodel + ch*8;
            uint32_t sw = ((ch ^ (row & 7)) << 4);
            CPA16(Kb + row*128 + sw, gk);
            CPA16(Vb + row*128 + sw, gk + Dmodel);
        }
        CPA_COMMIT();
        asm volatile("cp.async.wait_group 0;");
        __syncthreads();

        // S = Q @ K^T
        float sacc[8][4];
#pragma unroll
        for (int nt = 0; nt < 8; nt++)
#pragma unroll
            for (int q = 0; q < 4; q++) sacc[nt][q] = 0.f;
#pragma unroll
        for (int ks = 0; ks < 4; ks++) {
#pragma unroll
            for (int np = 0; np < 4; np++) {
                int key = (np*2 + lh)*8 + l7;
                int ch = ks*2 + ((lane >> 3) & 1);
                uint32_t bf[4];
                ldsm4(bf, Kb + key*128 + ((ch ^ l7) << 4));
                mma16(sacc[2*np  ], qa[ks], bf[0], bf[1]);
                mma16(sacc[2*np+1], qa[ks], bf[2], bf[3]);
            }
        }

        // scale + bias + online softmax (fp32)
        float rmax0 = -1e30f, rmax1 = -1e30f;
#pragma unroll
        for (int nt = 0; nt < 8; nt++) {
            const int kg = k0 + nt*8 + 2*cc;
            int i00 = min(max(kg     - qg0 + (MAXDIST-1), 0), 2*MAXDIST-2);
            int i01 = min(max(kg + 1 - qg0 + (MAXDIST-1), 0), 2*MAXDIST-2);
            int i10 = min(max(kg     - qg1 + (MAXDIST-1), 0), 2*MAXDIST-2);
            int i11 = min(max(kg + 1 - qg1 + (MAXDIST-1), 0), 2*MAXDIST-2);
            sacc[nt][0] = fmaf(sacc[nt][0], scale, Bias[i00]);
            sacc[nt][1] = fmaf(sacc[nt][1], scale, Bias[i01]);
            sacc[nt][2] = fmaf(sacc[nt][2], scale, Bias[i10]);
            sacc[nt][3] = fmaf(sacc[nt][3], scale, Bias[i11]);
            rmax0 = fmaxf(rmax0, fmaxf(sacc[nt][0], sacc[nt][1]));
            rmax1 = fmaxf(rmax1, fmaxf(sacc[nt][2], sacc[nt][3]));
        }
#pragma unroll
        for (int o = 1; o <= 2; o <<= 1) {
            rmax0 = fmaxf(rmax0, __shfl_xor_sync(0xffffffffu, rmax0, o));
            rmax1 = fmaxf(rmax1, __shfl_xor_sync(0xffffffffu, rmax1, o));
        }
        const float mn0 = fmaxf(m0v, rmax0);
        const float mn1 = fmaxf(m1v, rmax1);
        const float corr0 = __expf(m0v - mn0);
        const float corr1 = __expf(m1v - mn1);
        m0v = mn0; m1v = mn1;

        float rsum0 = 0.f, rsum1 = 0.f;
#pragma unroll
        for (int nt = 0; nt < 8; nt++) {
            float p00 = __expf(sacc[nt][0] - mn0);
            float p01 = __expf(sacc[nt][1] - mn0);
            float p10 = __expf(sacc[nt][2] - mn1);
            float p11 = __expf(sacc[nt][3] - mn1);
            rsum0 += p00 + p01;
            rsum1 += p10 + p11;
            uint32_t sw = ((nt ^ r) << 4) + 4*cc;
            *(__half2*)((char*)Ps + (wr + r    )*128 + sw) = __floats2half2_rn(p00, p01);
            *(__half2*)((char*)Ps + (wr + r + 8)*128 + sw) = __floats2half2_rn(p10, p11);
        }
#pragma unroll
        for (int o = 1; o <= 2; o <<= 1) {
            rsum0 += __shfl_xor_sync(0xffffffffu, rsum0, o);
            rsum1 += __shfl_xor_sync(0xffffffffu, rsum1, o);
        }
        l0 = l0*corr0 + rsum0;
        l1 = l1*corr1 + rsum1;
#pragma unroll
        for (int nt = 0; nt < 8; nt++) {
            oacc[nt][0] *= corr0; oacc[nt][1] *= corr0;
            oacc[nt][2] *= corr1; oacc[nt][3] *= corr1;
        }
        __syncwarp();

        // O += P @ V
#pragma unroll
        for (int ks = 0; ks < 4; ks++) {
            uint32_t pf[4];
            {
                int row = wr + l15;
                ldsm4(pf, Pb + row*128 + (((ks*2 + lh) ^ l7) << 4));
            }
#pragma unroll
            for (int p = 0; p < 4; p++) {
                int kk = ks*16 + l15;
                int ch = p*2 + lh;
                uint32_t bf[4];
                ldsm4t(bf, Vb + kk*128 + ((ch ^ l7) << 4));
                mma16(oacc[2*p  ], pf, bf[0], bf[1]);
                mma16(oacc[2*p+1], pf, bf[2], bf[3]);
            }
        }
        __syncthreads();
    }

    const float inv0 = 1.f / l0;
    const float inv1 = 1.f / l1;
    __half* c0p = ctx + (size_t)(b*Lseq + qg0)*Dmodel + h*HDdim;
    __half* c1p = ctx + (size_t)(b*Lseq + qg1)*Dmodel + h*HDdim;
#pragma unroll
    for (int nt = 0; nt < 8; nt++) {
        const int col = nt*8 + 2*cc;
        *(__half2*)&c0p[col] = __floats2half2_rn(oacc[nt][0]*inv0, oacc[nt][1]*inv0);
        *(__half2*)&c1p[col] = __floats2half2_rn(oacc[nt][2]*inv1, oacc[nt][3]*inv1);
    }
}

// ---------------------------------------------------------------------------
// LayerNorm over rows of 1024; optional fp16 secondary output.
// ---------------------------------------------------------------------------
__global__ __launch_bounds__(256)
void ln_kernel(const float* __restrict__ in, const float* __restrict__ gamma,
               const float* __restrict__ beta, float* __restrict__ out,
               __half* __restrict__ out16)
{
    __shared__ float red[16];
    const int row = blockIdx.x;
    const int tid = threadIdx.x;
    float4 v = ((const float4*)(in + (size_t)row*Dmodel))[tid];
    float s  = v.x + v.y + v.z + v.w;
    float sq = v.x*v.x + v.y*v.y + v.z*v.z + v.w*v.w;
#pragma unroll
    for (int o = 16; o >= 1; o >>= 1) {
        s  += __shfl_xor_sync(0xffffffffu, s,  o);
        sq += __shfl_xor_sync(0xffffffffu, sq, o);
    }
    const int wid = tid >> 5, lane = tid & 31;
    if (lane == 0) { red[wid] = s; red[wid+8] = sq; }
    __syncthreads();
    if (tid < 32) {
        float s2 = (lane < 8) ? red[lane]   : 0.f;
        float q2 = (lane < 8) ? red[lane+8] : 0.f;
#pragma unroll
        for (int o = 4; o >= 1; o >>= 1) {
            s2 += __shfl_xor_sync(0xffffffffu, s2, o);
            q2 += __shfl_xor_sync(0xffffffffu, q2, o);
        }
        if (lane == 0) { red[0] = s2; red[1] = q2; }
    }
    __syncthreads();
    const float mu  = red[0] * (1.f/Dmodel);
    const float var = red[1] * (1.f/Dmodel) - mu*mu;
    const float inv = rsqrtf(var + 1e-5f);
    const float4 g  = ((const float4*)gamma)[tid];
    const float4 be = ((const float4*)beta)[tid];
    float4 o;
    o.x = (v.x - mu)*inv*g.x + be.x;
    o.y = (v.y - mu)*inv*g.y + be.y;
    o.z = (v.z - mu)*inv*g.z + be.z;
    o.w = (v.w - mu)*inv*g.w + be.w;
    ((float4*)(out + (size_t)row*Dmodel))[tid] = o;
    if (out16) {
        __half2* o2 = (__half2*)(out16 + (size_t)row*Dmodel);
        o2[2*tid  ] = __floats2half2_rn(o.x, o.y);
        o2[2*tid+1] = __floats2half2_rn(o.z, o.w);
    }
}

// ---------------------------------------------------------------------------
extern "C" void kernel_launch(void* const* d_in, const int* in_sizes, int n_in,
                              void* d_out, int out_size)
{
    const float* x          = (const float*)d_in[0];
    const float* w_qkv      = (const float*)d_in[1];
    const float* w_out      = (const float*)d_in[2];
    const float* b_out      = (const float*)d_in[3];
    const float* bias_table = (const float*)d_in[4];
    const float* gamma1     = (const float*)d_in[5];
    const float* beta1      = (const float*)d_in[6];
    const float* w_ff1      = (const float*)d_in[7];
    const float* b_ff1      = (const float*)d_in[8];
    const float* w_ff2      = (const float*)d_in[9];
    const float* b_ff2      = (const float*)d_in[10];
    const float* gamma2     = (const float*)d_in[11];
    const float* beta2      = (const float*)d_in[12];
    float* out = (float*)d_out;

    __half *hx, *hwqkv, *hwout, *hwff1, *hwff2, *hqkv, *hctx, *hx1, *hhb;
    float *tmp, *x1f;
    cudaGetSymbolAddress((void**)&hx,    h_x);
    cudaGetSymbolAddress((void**)&hwqkv, h_wqkv);
    cudaGetSymbolAddress((void**)&hwout, h_wout);
    cudaGetSymbolAddress((void**)&hwff1, h_wff1);
    cudaGetSymbolAddress((void**)&hwff2, h_wff2);
    cudaGetSymbolAddress((void**)&hqkv,  h_qkv);
    cudaGetSymbolAddress((void**)&hctx,  h_ctx);
    cudaGetSymbolAddress((void**)&hx1,   h_x1);
    cudaGetSymbolAddress((void**)&hhb,   h_hb);
    cudaGetSymbolAddress((void**)&tmp,   g_tmp);
    cudaGetSymbolAddress((void**)&x1f,   g_x1f);

    cudaFuncSetAttribute(gemm_f16<0,1>,
                         cudaFuncAttributeMaxDynamicSharedMemorySize, G_SMEM);
    cudaFuncSetAttribute(gemm_f16<1,0>,
                         cudaFuncAttributeMaxDynamicSharedMemorySize, G_SMEM);
    cudaFuncSetAttribute(gemm_f16<2,1>,
                         cudaFuncAttributeMaxDynamicSharedMemorySize, G_SMEM);

    const int M = Mrows;  // 8192

    // fp32 -> fp16 conversions
    auto cvt = [&](const float* src, __half* dst, int n) {
        int n4 = n >> 2;
        cvt_f16<<<(n4 + 255)/256, 256>>>((const float4*)src, (__half2*)dst, n4);
    };
    cvt(x,     hx,    M*Dmodel);
    cvt(w_qkv, hwqkv, Dmodel*3*Dmodel);
    cvt(w_out, hwout, Dmodel*Dmodel);
    cvt(w_ff1, hwff1, Dmodel*DffDim);
    cvt(w_ff2, hwff2, DffDim*Dmodel);

    // 1. qkv = x @ w_qkv  (fp16 out)
    gemm_f16<0,1><<<dim3(3*Dmodel/128, M/128), 256, G_SMEM>>>(
        hx, hwqkv, nullptr, hqkv, M, 3*Dmodel, Dmodel, nullptr, nullptr);

    // 2. attention -> ctx (fp16)
    flash_attn_f16<<<dim3(Lseq/64, Bsz*Hheads), 128>>>(hqkv, bias_table, hctx);

    // 3. tmp = ctx @ w_out + b_out + x (fp32)
    gemm_f16<1,0><<<dim3(Dmodel/128, M/128), 256, G_SMEM>>>(
        hctx, hwout, tmp, nullptr, M, Dmodel, Dmodel, b_out, x);

    // 4. x1 = LN(tmp)  (fp32 + fp16)
    ln_kernel<<<M, 256>>>(tmp, gamma1, beta1, x1f, hx1);

    // 5. hb = GELU(x1 @ w_ff1 + b_ff1)  (fp16 out)
    gemm_f16<2,1><<<dim3(DffDim/128, M/128), 256, G_SMEM>>>(
        hx1, hwff1, nullptr, hhb, M, DffDim, Dmodel, b_ff1, nullptr);

    // 6. tmp = hb @ w_ff2 + b_ff2 + x1 (fp32)
    gemm_f16<1,0><<<dim3(Dmodel/128, M/128), 256, G_SMEM>>>(
        hhb, hwff2, tmp, nullptr, M, Dmodel, DffDim, b_ff2, x1f);

    // 7. out = LN(tmp)
    ln_kernel<<<M, 256>>>(tmp, gamma2, beta2, out, nullptr);
}